// round 1
// baseline (speedup 1.0000x reference)
#include <cuda_runtime.h>
#include <cuda_bf16.h>

// Problem constants
#define BB 16
#define TT 24
#define NN 2048
#define FF 64
#define BT (BB*TT)          // 384
#define NF (NN*FF)          // 131072
#define NF4 (NF/4)          // 32768
#define KSPLIT 8

// Scratch (device globals; no allocation allowed). All fully overwritten each call.
__device__ float d_rhs[BT*NN];        // 3 MB
__device__ float d_lf [BT*FF];        // lhs_f
__device__ float d_Gp [KSPLIT*BT*FF]; // K-split partials of G
__device__ float d_A  [BB*TT*TT];     // attention weights

// ---------------------------------------------------------------------------
// Kernel 1: one pass over x. Per (b,t) block:
//   lhs_f[f] = sum_n x[n,f]*U1[n]        (per-lane register accum, smem reduce)
//   rhs[n]   = sum_f x[n,f]*U3[f]        (half-warp shuffle reduce per row)
// Layout: warp w owns rows [w*256, w*256+256). Each iteration handles 2 rows:
// lanes 0-15 row (even), lanes 16-31 row (odd); each lane loads float4 at
// f = (lane&15)*4, so a warp reads 512 contiguous bytes per iteration.
// ---------------------------------------------------------------------------
__global__ __launch_bounds__(256) void k1_pass(
    const float* __restrict__ x, const float* __restrict__ U1,
    const float* __restrict__ U3, float* __restrict__ rhs, float* __restrict__ lf)
{
    const int bt   = blockIdx.x;
    const int w    = threadIdx.x >> 5;
    const int lane = threadIdx.x & 31;
    const int hl   = lane & 15;        // lane within half-warp
    const int half = lane >> 4;        // 0 or 1
    const float* xb = x + (size_t)bt * NF;

    const float4 u3 = *(const float4*)(U3 + hl*4);
    float4 acc = make_float4(0.f, 0.f, 0.f, 0.f);

    const int n0 = w * 256;
    #pragma unroll 4
    for (int k = 0; k < 128; k++) {
        const int n = n0 + 2*k + half;
        float4 v = *(const float4*)(xb + (size_t)n*FF + hl*4);
        const float u1 = __ldg(U1 + n);
        acc.x += v.x*u1; acc.y += v.y*u1; acc.z += v.z*u1; acc.w += v.w*u1;
        float d = v.x*u3.x + v.y*u3.y + v.z*u3.z + v.w*u3.w;
        // reduce within 16-lane group
        d += __shfl_down_sync(0xffffffffu, d, 8, 16);
        d += __shfl_down_sync(0xffffffffu, d, 4, 16);
        d += __shfl_down_sync(0xffffffffu, d, 2, 16);
        d += __shfl_down_sync(0xffffffffu, d, 1, 16);
        if (hl == 0) rhs[bt*NN + n] = d;
    }

    __shared__ float s[16][FF];
    const int pi = w*2 + half;
    s[pi][hl*4+0] = acc.x; s[pi][hl*4+1] = acc.y;
    s[pi][hl*4+2] = acc.z; s[pi][hl*4+3] = acc.w;
    __syncthreads();
    if (threadIdx.x < FF) {
        float t = 0.f;
        #pragma unroll
        for (int p = 0; p < 16; p++) t += s[p][threadIdx.x];
        lf[bt*FF + threadIdx.x] = t;
    }
}

// ---------------------------------------------------------------------------
// Kernel 2: G = rhs(384 x 2048) @ U2(2048 x 64), K-split into 8 partials.
// grid = (12 row-blocks of 32, 8 k-slices of 256). 256 threads.
// Thread (f = tid&63, rg = tid>>6) computes 8 rows x 1 col.
// ---------------------------------------------------------------------------
__global__ __launch_bounds__(256) void k2_gemm(
    const float* __restrict__ rhs, const float* __restrict__ U2,
    float* __restrict__ Gp)
{
    __shared__ float Us[64*64];
    __shared__ float Rs[32*65];
    const int m0 = blockIdx.x * 32;
    const int k0 = blockIdx.y * 256;
    const int f  = threadIdx.x & 63;
    const int rg = threadIdx.x >> 6;

    float acc[8];
    #pragma unroll
    for (int r = 0; r < 8; r++) acc[r] = 0.f;

    for (int kc = 0; kc < 256; kc += 64) {
        const int kb = k0 + kc;
        __syncthreads();
        #pragma unroll
        for (int i = 0; i < 16; i++) {
            int e = threadIdx.x + i*256;
            Us[e] = U2[(size_t)(kb + (e>>6))*FF + (e & 63)];
        }
        #pragma unroll
        for (int i = 0; i < 8; i++) {
            int e = threadIdx.x + i*256;
            int row = e >> 6, kk = e & 63;
            Rs[row*65 + kk] = rhs[(size_t)(m0+row)*NN + kb + kk];
        }
        __syncthreads();
        #pragma unroll
        for (int kk = 0; kk < 64; kk++) {
            const float u = Us[kk*64 + f];
            #pragma unroll
            for (int r = 0; r < 8; r++)
                acc[r] += Rs[(rg*8 + r)*65 + kk] * u;
        }
    }
    float* g = Gp + (size_t)blockIdx.y * (BT*FF);
    #pragma unroll
    for (int r = 0; r < 8; r++)
        g[(m0 + rg*8 + r)*FF + f] = acc[r];
}

// ---------------------------------------------------------------------------
// Kernel 3: per batch b (16 blocks, 576 threads):
//   product[t,s] = lhs_f[b,t,:] . G[b,s,:]   (sum K-split partials of G)
//   sig = sigmoid(product + be); E = Ve @ sig; A = softmax over t (columns).
// ---------------------------------------------------------------------------
__global__ __launch_bounds__(576) void k3_scores(
    const float* __restrict__ lf, const float* __restrict__ Gp,
    const float* __restrict__ be, const float* __restrict__ Ve,
    float* __restrict__ A)
{
    const int b = blockIdx.x;
    __shared__ float lfs[TT*65], Gs[TT*65], sg[TT*25], Em[TT*25];
    __shared__ float cmax[TT], csum[TT];
    const int tid = threadIdx.x;

    for (int e = tid; e < TT*FF; e += 576) {
        int t = e >> 6, f = e & 63;
        lfs[t*65 + f] = lf[(b*TT + t)*FF + f];
        float g = 0.f;
        #pragma unroll
        for (int ks = 0; ks < KSPLIT; ks++)
            g += Gp[(size_t)ks*(BT*FF) + (b*TT + t)*FF + f];
        Gs[t*65 + f] = g;
    }
    __syncthreads();

    const int t = tid / TT;
    const int s = tid % TT;
    float p = 0.f;
    #pragma unroll
    for (int f = 0; f < FF; f++)
        p += lfs[t*65 + f] * Gs[s*65 + f];
    sg[t*25 + s] = 1.f / (1.f + __expf(-(p + be[t*TT + s])));
    __syncthreads();

    // E[t][r] with r := s
    float e = 0.f;
    #pragma unroll
    for (int s2 = 0; s2 < TT; s2++)
        e += Ve[t*TT + s2] * sg[s2*25 + s];
    Em[t*25 + s] = e;
    __syncthreads();

    if (t == 0) {
        float m = -1e30f;
        #pragma unroll
        for (int tt2 = 0; tt2 < TT; tt2++) m = fmaxf(m, Em[tt2*25 + s]);
        cmax[s] = m;
    }
    __syncthreads();
    const float ex = __expf(Em[t*25 + s] - cmax[s]);
    Em[t*25 + s] = ex;
    __syncthreads();
    if (t == 0) {
        float sm = 0.f;
        #pragma unroll
        for (int tt2 = 0; tt2 < TT; tt2++) sm += Em[tt2*25 + s];
        csum[s] = sm;
    }
    __syncthreads();
    A[b*TT*TT + t*TT + s] = ex / csum[s];
}

// ---------------------------------------------------------------------------
// Kernel 4: out[b,s,nf] = sum_t x[b,t,nf] * A[b,t,s].
// Each thread holds 24 float4 of x in registers (read x once, write out once).
// grid = (NF4/256 = 128, B). A tile in smem (uniform broadcast reads).
// ---------------------------------------------------------------------------
__global__ __launch_bounds__(256) void k4_out(
    const float4* __restrict__ x4, const float* __restrict__ A,
    float4* __restrict__ out4)
{
    __shared__ float As[TT*TT];
    const int b = blockIdx.y;
    for (int i = threadIdx.x; i < TT*TT; i += 256)
        As[i] = A[b*TT*TT + i];
    __syncthreads();

    const size_t c = (size_t)blockIdx.x * 256 + threadIdx.x;  // float4 column
    const float4* xb = x4 + (size_t)b * TT * NF4 + c;

    float4 xr[TT];
    #pragma unroll
    for (int t = 0; t < TT; t++) xr[t] = xb[(size_t)t * NF4];

    float4* ob = out4 + (size_t)b * TT * NF4 + c;
    #pragma unroll 4
    for (int s = 0; s < TT; s++) {
        float4 acc = make_float4(0.f, 0.f, 0.f, 0.f);
        #pragma unroll
        for (int t = 0; t < TT; t++) {
            const float a = As[t*TT + s];
            acc.x += xr[t].x * a; acc.y += xr[t].y * a;
            acc.z += xr[t].z * a; acc.w += xr[t].w * a;
        }
        ob[(size_t)s * NF4] = acc;
    }
}

// ---------------------------------------------------------------------------
extern "C" void kernel_launch(void* const* d_in, const int* in_sizes, int n_in,
                              void* d_out, int out_size)
{
    const float* x  = (const float*)d_in[0];  // (16,24,2048,64)
    const float* U1 = (const float*)d_in[1];  // (2048)
    const float* U2 = (const float*)d_in[2];  // (2048,64)
    const float* U3 = (const float*)d_in[3];  // (64)
    const float* be = (const float*)d_in[4];  // (24,24)
    const float* Ve = (const float*)d_in[5];  // (24,24)
    float* out = (float*)d_out;

    float *rhs, *lf, *Gp, *A;
    cudaGetSymbolAddress((void**)&rhs, d_rhs);
    cudaGetSymbolAddress((void**)&lf,  d_lf);
    cudaGetSymbolAddress((void**)&Gp,  d_Gp);
    cudaGetSymbolAddress((void**)&A,   d_A);

    k1_pass<<<BT, 256>>>(x, U1, U3, rhs, lf);
    k2_gemm<<<dim3(BT/32, KSPLIT), 256>>>(rhs, U2, Gp);
    k3_scores<<<BB, 576>>>(lf, Gp, be, Ve, A);
    k4_out<<<dim3(NF4/256, BB), 256>>>((const float4*)x, A, (float4*)out);
}